// round 16
// baseline (speedup 1.0000x reference)
#include <cuda_runtime.h>
#include <cstdint>

// ---------------- problem constants ----------------
#define TOKS   32768
#define DIMD   128
#define KCB    8192
#define TM     128              // tokens per CTA
#define NQ     4                // codebook slices (1024 CTAs)
#define QCODES (KCB / NQ)       // 2048
#define CHUNK  64               // codes per B chunk (16KB stage)
#define NCHUNK (QCODES / CHUNK) // 32
#define NTILES (TOKS / TM)      // 256
#define NGROUP (NQ * 4)         // candidate groups: q x warp_n
#define NCAND  (NGROUP * 2)     // 32 candidates per token
#define BIAS   512.0f
#define TAU    0.6f             // rescore window (bf16 noise + 7-bit id quant)

#define A_BYTES      32768      // packed A: 8 mb * 8 ks * 32 lanes * 16B
#define BSTAGE_BYTES 16384      // packed B chunk (64 codes)
#define CN_OFF       (A_BYTES + 2 * BSTAGE_BYTES)      // 65536
#define SMEM_TOTAL   (CN_OFF + QCODES * 4)             // 73728 (3 CTAs/SM)

__device__ float  g_cnorm[KCB];             // raw ||c||^2 (rescore)
__device__ float  g_cnormb[KCB];            // ||c||^2 + BIAS (acc init)
__device__ uint4  g_cb_pk[(KCB / 8) * 4 * 32];  // fragment-packed bf16 codebook
__device__ float2 g_bd2[NGROUP * TOKS];     // per-group screened top-2 dists
__device__ int2   g_bi2[NGROUP * TOKS];     // per-group screened top-2 codes
__device__ int    g_idx[TOKS];              // final winners

// ---------------- PTX helpers (baseline sm_80+) ----------------
__device__ __forceinline__ uint32_t bf16x2(float hi, float lo) {
    uint32_t r;
    asm("cvt.rn.bf16x2.f32 %0, %1, %2;" : "=r"(r) : "f"(hi), "f"(lo));
    return r;
}
__device__ __forceinline__ void cp_async16(uint32_t saddr, const void* gptr) {
    asm volatile("cp.async.cg.shared.global [%0], [%1], 16;"
                 :: "r"(saddr), "l"(gptr) : "memory");
}
#define CP_COMMIT() asm volatile("cp.async.commit_group;" ::: "memory")
#define CP_WAIT1()  asm volatile("cp.async.wait_group 1;" ::: "memory")
#define CP_WAIT0()  asm volatile("cp.async.wait_group 0;" ::: "memory")

__device__ __forceinline__ void mma_bf16(float* d, uint4 a,
                                         uint32_t b0, uint32_t b1) {
    asm volatile(
        "mma.sync.aligned.m16n8k16.row.col.f32.bf16.bf16.f32 "
        "{%0,%1,%2,%3}, {%4,%5,%6,%7}, {%8,%9}, {%0,%1,%2,%3};"
        : "+f"(d[0]), "+f"(d[1]), "+f"(d[2]), "+f"(d[3])
        : "r"(a.x), "r"(a.y), "r"(a.z), "r"(a.w), "r"(b0), "r"(b1));
}

__device__ __forceinline__ void ins2(uint32_t& a, uint32_t& b, uint32_t u) {
    uint32_t mx = a > u ? a : u;
    a = a < u ? a : u;
    b = b < mx ? b : mx;
}
__device__ __forceinline__ bool cmpdc(float d1, int c1, float d2, int c2) {
    return d1 < d2 || (d1 == d2 && c1 < c2);
}
__device__ __forceinline__ void merge2(float& a1, int& i1, float& a2, int& i2,
                                       float b1, int j1, float b2, int j2) {
    bool t = cmpdc(a1, i1, b1, j1);
    float m1 = t ? a1 : b1;  int mi1 = t ? i1 : j1;
    float x1 = t ? b1 : a1;  int xi1 = t ? j1 : i1;
    float x2 = t ? a2 : b2;  int xi2 = t ? i2 : j2;
    bool t2 = cmpdc(x2, xi2, x1, xi1);
    a1 = m1; i1 = mi1;
    a2 = t2 ? x2 : x1; i2 = t2 ? xi2 : xi1;
}

// ---------------- prep: fragment-packed bf16 codebook + norms (fused) ----------------
__global__ __launch_bounds__(256) void prep_kernel(const float* __restrict__ cb) {
    int nb = (blockIdx.x * blockDim.x + threadIdx.x) >> 5;
    int lane = threadIdx.x & 31;
    if (nb >= KCB / 8) return;
    int g = lane >> 2, tg = lane & 3;
    const float* row = cb + (size_t)(nb * 8 + g) * DIMD;
    float s = 0.f;
#pragma unroll
    for (int ks2 = 0; ks2 < 4; ++ks2) {
        int k0 = ks2 * 32;
        float2 a = *(const float2*)&row[k0 + 2 * tg];
        float2 b = *(const float2*)&row[k0 + 8 + 2 * tg];
        float2 c = *(const float2*)&row[k0 + 16 + 2 * tg];
        float2 d = *(const float2*)&row[k0 + 24 + 2 * tg];
        s = fmaf(a.x, a.x, s); s = fmaf(a.y, a.y, s);
        s = fmaf(b.x, b.x, s); s = fmaf(b.y, b.y, s);
        s = fmaf(c.x, c.x, s); s = fmaf(c.y, c.y, s);
        s = fmaf(d.x, d.x, s); s = fmaf(d.y, d.y, s);
        uint4 u;
        u.x = bf16x2(a.y, a.x); u.y = bf16x2(b.y, b.x);
        u.z = bf16x2(c.y, c.x); u.w = bf16x2(d.y, d.x);
        g_cb_pk[((size_t)nb * 4 + ks2) * 32 + lane] = u;
    }
    s += __shfl_xor_sync(0xffffffffu, s, 1);
    s += __shfl_xor_sync(0xffffffffu, s, 2);
    if (tg == 0) {
        g_cnorm[nb * 8 + g] = s;
        g_cnormb[nb * 8 + g] = s + BIAS;
    }
}

// ---------------- main VQ kernel (3 CTAs/SM, 64-code chunks) ----------------
__global__ __launch_bounds__(256, 3) void vq_kernel(const float* __restrict__ ze)
{
    extern __shared__ char smem[];
    uint4* Apk = (uint4*)smem;
    float* scn = (float*)(smem + CN_OFF);     // cn table for this q slice

    const int t      = threadIdx.x;
    const int lane   = t & 31;
    const int wid    = t >> 5;
    const int g      = lane >> 2;
    const int tg     = lane & 3;
    const int warp_m = wid >> 2;
    const int warp_n = wid & 3;

    const int tile  = blockIdx.x >> 2;
    const int q     = blockIdx.x & 3;
    const int tok0  = tile * TM;
    const int cbase = q * QCODES;

    // ---- issue B chunk-0 prefetch FIRST (overlaps all of prologue) ----
    {
        uint32_t bb = (uint32_t)__cvta_generic_to_shared(smem + A_BYTES);
        const char* src = (const char*)&g_cb_pk[((size_t)cbase >> 3) * 4 * 32];
#pragma unroll
        for (int i = 0; i < 4; ++i)
            cp_async16(bb + (uint32_t)(i * 256 + t) * 16, src + (i * 256 + t) * 16);
        CP_COMMIT();
    }

    // ---- stage cn slice to smem (once) ----
#pragma unroll
    for (int i = 0; i < QCODES / 256; ++i)
        scn[i * 256 + t] = g_cnormb[cbase + i * 256 + t];

    // ---- pack A = bf16(-2*ze) in fragment order via direct LDG ----
    {
        const int mb = wid;
        const float* r0p = ze + (size_t)(tok0 + mb * 16 + g) * DIMD;
        const float* r1p = r0p + 8 * DIMD;
#pragma unroll
        for (int ks = 0; ks < 8; ++ks) {
            int c0 = ks * 16 + 2 * tg, c1 = c0 + 8;
            float2 v00 = *(const float2*)&r0p[c0];
            float2 v10 = *(const float2*)&r1p[c0];
            float2 v01 = *(const float2*)&r0p[c1];
            float2 v11 = *(const float2*)&r1p[c1];
            uint4 u;
            u.x = bf16x2(-2.f * v00.y, -2.f * v00.x);
            u.y = bf16x2(-2.f * v10.y, -2.f * v10.x);
            u.z = bf16x2(-2.f * v01.y, -2.f * v01.x);
            u.w = bf16x2(-2.f * v11.y, -2.f * v11.x);
            Apk[(mb * 8 + ks) * 32 + lane] = u;
        }
    }
    __syncthreads();

    uint32_t top1[8], top2v[8];
#pragma unroll
    for (int s = 0; s < 8; ++s) { top1[s] = 0xFFFFFFFFu; top2v[s] = 0xFFFFFFFFu; }

    const uint32_t MASK = 0xFFFFFF80u;   // 7-bit local id (128 ids: 32 ch * 4)

    for (int ch = 0; ch < NCHUNK; ++ch) {
        if (ch + 1 < NCHUNK) {
            uint32_t bb = (uint32_t)__cvta_generic_to_shared(
                smem + A_BYTES + ((ch + 1) & 1) * BSTAGE_BYTES);
            const char* src = (const char*)
                &g_cb_pk[((size_t)(cbase + (ch + 1) * CHUNK) >> 3) * 4 * 32];
#pragma unroll
            for (int i = 0; i < 4; ++i)
                cp_async16(bb + (uint32_t)(i * 256 + t) * 16,
                           src + (i * 256 + t) * 16);
            CP_COMMIT(); CP_WAIT1();
        } else {
            CP_WAIT0();
        }
        __syncthreads();

        const uint4* bs = (const uint4*)(smem + A_BYTES + (ch & 1) * BSTAGE_BYTES);

        // cn from smem (broadcast LDS) — acc init rides MMA accumulate
        float acc[4][2][4];
#pragma unroll
        for (int nt = 0; nt < 2; ++nt) {
            float2 cn = *(const float2*)
                &scn[ch * CHUNK + (warp_n * 2 + nt) * 8 + 2 * tg];
#pragma unroll
            for (int mt = 0; mt < 4; ++mt) {
                acc[mt][nt][0] = cn.x;
                acc[mt][nt][1] = cn.y;
                acc[mt][nt][2] = cn.x;
                acc[mt][nt][3] = cn.y;
            }
        }

#pragma unroll
        for (int ks2 = 0; ks2 < 4; ++ks2) {
            uint4 B4[2];
#pragma unroll
            for (int nt = 0; nt < 2; ++nt)
                B4[nt] = bs[(((warp_n * 2 + nt) * 4) + ks2) * 32 + lane];
            uint4 A4[4];
#pragma unroll
            for (int mt = 0; mt < 4; ++mt)
                A4[mt] = Apk[((warp_m * 4 + mt) * 8 + 2 * ks2) * 32 + lane];
#pragma unroll
            for (int mt = 0; mt < 4; ++mt)
#pragma unroll
                for (int nt = 0; nt < 2; ++nt)
                    mma_bf16(acc[mt][nt], A4[mt], B4[nt].x, B4[nt].y);
#pragma unroll
            for (int mt = 0; mt < 4; ++mt)
                A4[mt] = Apk[((warp_m * 4 + mt) * 8 + 2 * ks2 + 1) * 32 + lane];
#pragma unroll
            for (int mt = 0; mt < 4; ++mt)
#pragma unroll
                for (int nt = 0; nt < 2; ++nt)
                    mma_bf16(acc[mt][nt], A4[mt], B4[nt].z, B4[nt].w);
        }

        __syncthreads();   // all B reads done; stage reusable (fold is off-path)

        // ---- fold (after barrier): per-candidate top-2 insert (no pre-min) ----
#pragma unroll
        for (int nt = 0; nt < 2; ++nt) {
            uint32_t lidb = (uint32_t)(ch * 4 + nt * 2);
#pragma unroll
            for (int mt = 0; mt < 4; ++mt) {
                int s0 = mt * 2, s1 = s0 + 1;
                uint32_t u;
                u = (__float_as_uint(acc[mt][nt][0]) & MASK) | lidb;
                ins2(top1[s0], top2v[s0], u);
                u = (__float_as_uint(acc[mt][nt][1]) & MASK) | (lidb + 1);
                ins2(top1[s0], top2v[s0], u);
                u = (__float_as_uint(acc[mt][nt][2]) & MASK) | lidb;
                ins2(top1[s1], top2v[s1], u);
                u = (__float_as_uint(acc[mt][nt][3]) & MASK) | (lidb + 1);
                ins2(top1[s1], top2v[s1], u);
            }
        }
    }

    // ---- epilogue: decode, reduce over tg (shfl), direct global write ----
#pragma unroll
    for (int s = 0; s < 8; ++s) {
        float d1 = __uint_as_float(top1[s] & MASK);
        float d2 = __uint_as_float(top2v[s] & MASK);
        int l1 = (int)(top1[s] & 127u), l2 = (int)(top2v[s] & 127u);
        int c1 = cbase + (l1 >> 2) * CHUNK + warp_n * 16 + ((l1 >> 1) & 1) * 8
               + 2 * tg + (l1 & 1);
        int c2 = cbase + (l2 >> 2) * CHUNK + warp_n * 16 + ((l2 >> 1) & 1) * 8
               + 2 * tg + (l2 & 1);
#pragma unroll
        for (int off = 1; off < 4; off <<= 1) {
            float od1 = __shfl_xor_sync(0xffffffffu, d1, off);
            float od2 = __shfl_xor_sync(0xffffffffu, d2, off);
            int   oc1 = __shfl_xor_sync(0xffffffffu, c1, off);
            int   oc2 = __shfl_xor_sync(0xffffffffu, c2, off);
            merge2(d1, c1, d2, c2, od1, oc1, od2, oc2);
        }
        if (tg == 0) {
            int row = warp_m * 64 + (s >> 1) * 16 + g + (s & 1) * 8;
            int grp = q * 4 + warp_n;
            g_bd2[(size_t)grp * TOKS + tok0 + row] = make_float2(d1, d2);
            g_bi2[(size_t)grp * TOKS + tok0 + row] = make_int2(c1, c2);
        }
    }
}

// ---------------- merge groups + exact rescore (thread per token) ----------------
__global__ __launch_bounds__(256) void merge_kernel(
    const float* __restrict__ ze, const float* __restrict__ cb,
    float* __restrict__ out, int out_size)
{
    int tok = blockIdx.x * 256 + threadIdx.x;
    if (tok >= TOKS) return;

    float cv[NCAND]; int ci[NCAND];
#pragma unroll
    for (int gp = 0; gp < NGROUP; ++gp) {
        float2 dv = g_bd2[(size_t)gp * TOKS + tok];
        int2   iv = g_bi2[(size_t)gp * TOKS + tok];
        cv[gp * 2 + 0] = dv.x; ci[gp * 2 + 0] = iv.x;
        cv[gp * 2 + 1] = dv.y; ci[gp * 2 + 1] = iv.y;
    }
    float b1v = cv[0]; int b1i = ci[0];
#pragma unroll
    for (int j = 1; j < NCAND; ++j)
        if (cmpdc(cv[j], ci[j], b1v, b1i)) { b1v = cv[j]; b1i = ci[j]; }
    int nwin = 0;
#pragma unroll
    for (int j = 0; j < NCAND; ++j)
        if (cv[j] <= b1v + TAU) ++nwin;

    int winner = b1i;
    if (nwin > 1) {
        const float4* xr = (const float4*)(ze + (size_t)tok * DIMD);
        float bd = 3.4e38f; int bi = 0x7fffffff;
#pragma unroll 1
        for (int j = 0; j < NCAND; ++j) {
            if (cv[j] > b1v + TAU) continue;
            int c = ci[j];
            const float4* cr = (const float4*)(cb + (size_t)c * DIMD);
            float dot = 0.f;
#pragma unroll
            for (int k = 0; k < 32; ++k) {
                float4 a = xr[k], b = cr[k];
                dot = fmaf(a.x, b.x, dot);
                dot = fmaf(a.y, b.y, dot);
                dot = fmaf(a.z, b.z, dot);
                dot = fmaf(a.w, b.w, dot);
            }
            float d2 = fmaf(-2.f, dot, __ldg(&g_cnorm[c]));
            if (d2 < bd || (d2 == bd && c < bi)) { bd = d2; bi = c; }
        }
        winner = bi;
    }
    g_idx[tok] = winner;
    if (out_size > TOKS * DIMD)
        out[(size_t)TOKS * DIMD + tok] = (float)winner;
}

// ---------------- gather: warp per token (broadcast idx, coalesced copy) --------
__global__ __launch_bounds__(256) void gather_kernel(
    const float* __restrict__ cb, float* __restrict__ out)
{
    int gid  = blockIdx.x * 256 + threadIdx.x;   // one float4 per thread
    int tok  = gid >> 5;
    int lane = gid & 31;
    int idx  = __ldg(&g_idx[tok]);
    ((float4*)out)[gid] = ((const float4*)cb)[(size_t)idx * 32 + lane];
}

extern "C" void kernel_launch(void* const* d_in, const int* in_sizes, int n_in,
                              void* d_out, int out_size) {
    const float* ze = (const float*)d_in[0];
    const float* cb = (const float*)d_in[1];
    if (n_in >= 2 && in_sizes[0] == KCB * DIMD && in_sizes[1] == TOKS * DIMD) {
        const float* tmp = ze; ze = cb; cb = tmp;
    }

    cudaFuncSetAttribute(vq_kernel, cudaFuncAttributeMaxDynamicSharedMemorySize,
                         SMEM_TOTAL);

    prep_kernel<<<(KCB / 8) * 32 / 256, 256>>>(cb);
    vq_kernel<<<NTILES * NQ, 256, SMEM_TOTAL>>>(ze);
    merge_kernel<<<TOKS / 256, 256>>>(ze, cb, (float*)d_out, out_size);
    gather_kernel<<<TOKS * 32 / 256, 256>>>(cb, (float*)d_out);
}

// round 17
// speedup vs baseline: 1.1631x; 1.1631x over previous
#include <cuda_runtime.h>
#include <cstdint>

// ---------------- problem constants ----------------
#define TOKS   32768
#define DIMD   128
#define KCB    8192
#define TM     128              // tokens per CTA
#define NQ     4                // codebook slices (1024 CTAs)
#define QCODES (KCB / NQ)       // 2048
#define CHUNK  128              // codes per chunk
#define NCHUNK (QCODES / CHUNK) // 16
#define NTILES (TOKS / TM)      // 256
#define NGROUP (NQ * 4)         // candidate groups: q x warp_n
#define NCAND  (NGROUP * 2)     // 32 candidates per token
#define BIAS   512.0f
#define TAU    0.6f             // rescore window (bf16 noise + 7-bit id quant)

#define A_BYTES      32768      // packed A: 8 mb * 8 ks * 32 lanes * 16B
#define PAIR_BYTES   8192       // per-pair B slice: 4 nb * 4 ks * 32 lanes * 16B
#define B_OFF        A_BYTES    // 4 pairs * 2 stages * 8KB = 64KB
#define CN_OFF       (A_BYTES + 65536)                 // 98304
#define SMEM_TOTAL   (CN_OFF + QCODES * 4)             // 106496 (2 CTAs/SM)

__device__ float  g_cnorm[KCB];             // raw ||c||^2 (rescore)
__device__ float  g_cnormb[KCB];            // ||c||^2 + BIAS (acc init)
__device__ uint4  g_cb_pk[(KCB / 8) * 4 * 32];  // fragment-packed bf16 codebook
__device__ float2 g_bd2[NGROUP * TOKS];     // per-group screened top-2 dists
__device__ int2   g_bi2[NGROUP * TOKS];     // per-group screened top-2 codes
__device__ int    g_idx[TOKS];              // final winners

// ---------------- PTX helpers (baseline sm_80+) ----------------
__device__ __forceinline__ uint32_t bf16x2(float hi, float lo) {
    uint32_t r;
    asm("cvt.rn.bf16x2.f32 %0, %1, %2;" : "=r"(r) : "f"(hi), "f"(lo));
    return r;
}
__device__ __forceinline__ void cp_async16(uint32_t saddr, const void* gptr) {
    asm volatile("cp.async.cg.shared.global [%0], [%1], 16;"
                 :: "r"(saddr), "l"(gptr) : "memory");
}
#define CP_COMMIT() asm volatile("cp.async.commit_group;" ::: "memory")
#define CP_WAIT1()  asm volatile("cp.async.wait_group 1;" ::: "memory")
#define CP_WAIT0()  asm volatile("cp.async.wait_group 0;" ::: "memory")
#define BAR_PAIR(id) \
    asm volatile("bar.sync %0, 64;" :: "r"(id) : "memory")

__device__ __forceinline__ void mma_bf16(float* d, uint4 a,
                                         uint32_t b0, uint32_t b1) {
    asm volatile(
        "mma.sync.aligned.m16n8k16.row.col.f32.bf16.bf16.f32 "
        "{%0,%1,%2,%3}, {%4,%5,%6,%7}, {%8,%9}, {%0,%1,%2,%3};"
        : "+f"(d[0]), "+f"(d[1]), "+f"(d[2]), "+f"(d[3])
        : "r"(a.x), "r"(a.y), "r"(a.z), "r"(a.w), "r"(b0), "r"(b1));
}

__device__ __forceinline__ void ins2(uint32_t& a, uint32_t& b, uint32_t u) {
    uint32_t mx = a > u ? a : u;
    a = a < u ? a : u;
    b = b < mx ? b : mx;
}
__device__ __forceinline__ bool cmpdc(float d1, int c1, float d2, int c2) {
    return d1 < d2 || (d1 == d2 && c1 < c2);
}
__device__ __forceinline__ void merge2(float& a1, int& i1, float& a2, int& i2,
                                       float b1, int j1, float b2, int j2) {
    bool t = cmpdc(a1, i1, b1, j1);
    float m1 = t ? a1 : b1;  int mi1 = t ? i1 : j1;
    float x1 = t ? b1 : a1;  int xi1 = t ? j1 : i1;
    float x2 = t ? a2 : b2;  int xi2 = t ? i2 : j2;
    bool t2 = cmpdc(x2, xi2, x1, xi1);
    a1 = m1; i1 = mi1;
    a2 = t2 ? x2 : x1; i2 = t2 ? xi2 : xi1;
}

// ---------------- prep: fragment-packed bf16 codebook + norms (fused) ----------------
__global__ __launch_bounds__(256) void prep_kernel(const float* __restrict__ cb) {
    int nb = (blockIdx.x * blockDim.x + threadIdx.x) >> 5;
    int lane = threadIdx.x & 31;
    if (nb >= KCB / 8) return;
    int g = lane >> 2, tg = lane & 3;
    const float* row = cb + (size_t)(nb * 8 + g) * DIMD;
    float s = 0.f;
#pragma unroll
    for (int ks2 = 0; ks2 < 4; ++ks2) {
        int k0 = ks2 * 32;
        float2 a = *(const float2*)&row[k0 + 2 * tg];
        float2 b = *(const float2*)&row[k0 + 8 + 2 * tg];
        float2 c = *(const float2*)&row[k0 + 16 + 2 * tg];
        float2 d = *(const float2*)&row[k0 + 24 + 2 * tg];
        s = fmaf(a.x, a.x, s); s = fmaf(a.y, a.y, s);
        s = fmaf(b.x, b.x, s); s = fmaf(b.y, b.y, s);
        s = fmaf(c.x, c.x, s); s = fmaf(c.y, c.y, s);
        s = fmaf(d.x, d.x, s); s = fmaf(d.y, d.y, s);
        uint4 u;
        u.x = bf16x2(a.y, a.x); u.y = bf16x2(b.y, b.x);
        u.z = bf16x2(c.y, c.x); u.w = bf16x2(d.y, d.x);
        g_cb_pk[((size_t)nb * 4 + ks2) * 32 + lane] = u;
    }
    s += __shfl_xor_sync(0xffffffffu, s, 1);
    s += __shfl_xor_sync(0xffffffffu, s, 2);
    if (tg == 0) {
        g_cnorm[nb * 8 + g] = s;
        g_cnormb[nb * 8 + g] = s + BIAS;
    }
}

// ---------------- main VQ kernel (pair-scoped sync; no CTA barriers in loop) ----
__global__ __launch_bounds__(256, 2) void vq_kernel(const float* __restrict__ ze)
{
    extern __shared__ char smem[];
    uint4* Apk = (uint4*)smem;
    float* scn = (float*)(smem + CN_OFF);     // cn table for this q slice

    const int t      = threadIdx.x;
    const int lane   = t & 31;
    const int wid    = t >> 5;
    const int g      = lane >> 2;
    const int tg     = lane & 3;
    const int warp_m = wid >> 2;
    const int warp_n = wid & 3;
    const int pair   = warp_n;               // pair = {wid n, wid n+4}
    const int tp     = warp_m * 32 + lane;    // 0..63 within pair
    const int barid  = pair + 1;              // named barrier ids 1..4

    const int tile  = blockIdx.x >> 2;
    const int q     = blockIdx.x & 3;
    const int tok0  = tile * TM;
    const int cbase = q * QCODES;

    // per-pair B staging: [pair][stage] of 8KB
    const uint32_t bpair = (uint32_t)__cvta_generic_to_shared(smem + B_OFF)
                         + (uint32_t)pair * (2 * PAIR_BYTES);
    // gmem base for this pair's slice (256 bytes per code in packed layout)
    const char* gsrc = (const char*)g_cb_pk
                     + (size_t)(cbase + pair * 32) * 256;

    // ---- issue pair's chunk-0 prefetch FIRST (overlaps prologue) ----
#pragma unroll
    for (int i = 0; i < 8; ++i)
        cp_async16(bpair + (uint32_t)(i * 64 + tp) * 16,
                   gsrc + (i * 64 + tp) * 16);
    CP_COMMIT();

    // ---- stage cn slice to smem (once) ----
#pragma unroll
    for (int i = 0; i < QCODES / 256; ++i)
        scn[i * 256 + t] = g_cnormb[cbase + i * 256 + t];

    // ---- pack A = bf16(-2*ze) in fragment order via direct LDG ----
    {
        const int mb = wid;
        const float* r0p = ze + (size_t)(tok0 + mb * 16 + g) * DIMD;
        const float* r1p = r0p + 8 * DIMD;
#pragma unroll
        for (int ks = 0; ks < 8; ++ks) {
            int c0 = ks * 16 + 2 * tg, c1 = c0 + 8;
            float2 v00 = *(const float2*)&r0p[c0];
            float2 v10 = *(const float2*)&r1p[c0];
            float2 v01 = *(const float2*)&r0p[c1];
            float2 v11 = *(const float2*)&r1p[c1];
            uint4 u;
            u.x = bf16x2(-2.f * v00.y, -2.f * v00.x);
            u.y = bf16x2(-2.f * v10.y, -2.f * v10.x);
            u.z = bf16x2(-2.f * v01.y, -2.f * v01.x);
            u.w = bf16x2(-2.f * v11.y, -2.f * v11.x);
            Apk[(mb * 8 + ks) * 32 + lane] = u;
        }
    }
    __syncthreads();   // A + cn visible to all; only CTA-wide barrier

    uint32_t top1[8], top2v[8];
#pragma unroll
    for (int s = 0; s < 8; ++s) { top1[s] = 0xFFFFFFFFu; top2v[s] = 0xFFFFFFFFu; }

    const uint32_t MASK = 0xFFFFFF80u;   // 7-bit local id (128 ids: 16 ch * 8)

    for (int ch = 0; ch < NCHUNK; ++ch) {
        if (ch + 1 < NCHUNK) {
            uint32_t bb = bpair + (uint32_t)(((ch + 1) & 1) * PAIR_BYTES);
            const char* src = gsrc + (size_t)(ch + 1) * CHUNK * 256;
#pragma unroll
            for (int i = 0; i < 8; ++i)
                cp_async16(bb + (uint32_t)(i * 64 + tp) * 16,
                           src + (i * 64 + tp) * 16);
            CP_COMMIT(); CP_WAIT1();
        } else {
            CP_WAIT0();
        }
        BAR_PAIR(barid);    // pair's chunk data visible to both warps

        const uint4* bs = (const uint4*)(smem + B_OFF
                        + pair * (2 * PAIR_BYTES) + (ch & 1) * PAIR_BYTES);

        // cn from smem (broadcast LDS) — acc init rides MMA accumulate
        float acc[4][4][4];
#pragma unroll
        for (int nt = 0; nt < 4; ++nt) {
            float2 cn = *(const float2*)
                &scn[ch * CHUNK + warp_n * 32 + nt * 8 + 2 * tg];
#pragma unroll
            for (int mt = 0; mt < 4; ++mt) {
                acc[mt][nt][0] = cn.x;
                acc[mt][nt][1] = cn.y;
                acc[mt][nt][2] = cn.x;
                acc[mt][nt][3] = cn.y;
            }
        }

#pragma unroll
        for (int ks2 = 0; ks2 < 4; ++ks2) {
            uint4 B4[4];
#pragma unroll
            for (int nt = 0; nt < 4; ++nt)
                B4[nt] = bs[(nt * 4 + ks2) * 32 + lane];
            uint4 A4[4];
#pragma unroll
            for (int mt = 0; mt < 4; ++mt)
                A4[mt] = Apk[((warp_m * 4 + mt) * 8 + 2 * ks2) * 32 + lane];
#pragma unroll
            for (int mt = 0; mt < 4; ++mt)
#pragma unroll
                for (int nt = 0; nt < 4; ++nt)
                    mma_bf16(acc[mt][nt], A4[mt], B4[nt].x, B4[nt].y);
#pragma unroll
            for (int mt = 0; mt < 4; ++mt)
                A4[mt] = Apk[((warp_m * 4 + mt) * 8 + 2 * ks2 + 1) * 32 + lane];
#pragma unroll
            for (int mt = 0; mt < 4; ++mt)
#pragma unroll
                for (int nt = 0; nt < 4; ++nt)
                    mma_bf16(acc[mt][nt], A4[mt], B4[nt].z, B4[nt].w);
        }

        BAR_PAIR(barid);    // pair's reads done; stage reusable

        // ---- fold (off critical path): pre-min pair, single ins2 ----
#pragma unroll
        for (int nt = 0; nt < 4; ++nt) {
            uint32_t lidb = (uint32_t)(ch * 8 + nt * 2);
#pragma unroll
            for (int mt = 0; mt < 4; ++mt) {
                int s0 = mt * 2, s1 = s0 + 1;
                uint32_t u0 = (__float_as_uint(acc[mt][nt][0]) & MASK) | lidb;
                uint32_t u1 = (__float_as_uint(acc[mt][nt][1]) & MASK) | (lidb + 1);
                ins2(top1[s0], top2v[s0], min(u0, u1));
                uint32_t u2 = (__float_as_uint(acc[mt][nt][2]) & MASK) | lidb;
                uint32_t u3 = (__float_as_uint(acc[mt][nt][3]) & MASK) | (lidb + 1);
                ins2(top1[s1], top2v[s1], min(u2, u3));
            }
        }
    }

    // ---- epilogue: decode, reduce over tg (shfl), direct global write ----
#pragma unroll
    for (int s = 0; s < 8; ++s) {
        float d1 = __uint_as_float(top1[s] & MASK);
        float d2 = __uint_as_float(top2v[s] & MASK);
        int l1 = (int)(top1[s] & 127u), l2 = (int)(top2v[s] & 127u);
        int c1 = cbase + (l1 >> 3) * CHUNK + warp_n * 32 + ((l1 >> 1) & 3) * 8
               + 2 * tg + (l1 & 1);
        int c2 = cbase + (l2 >> 3) * CHUNK + warp_n * 32 + ((l2 >> 1) & 3) * 8
               + 2 * tg + (l2 & 1);
#pragma unroll
        for (int off = 1; off < 4; off <<= 1) {
            float od1 = __shfl_xor_sync(0xffffffffu, d1, off);
            float od2 = __shfl_xor_sync(0xffffffffu, d2, off);
            int   oc1 = __shfl_xor_sync(0xffffffffu, c1, off);
            int   oc2 = __shfl_xor_sync(0xffffffffu, c2, off);
            merge2(d1, c1, d2, c2, od1, oc1, od2, oc2);
        }
        if (tg == 0) {
            int row = warp_m * 64 + (s >> 1) * 16 + g + (s & 1) * 8;
            int grp = q * 4 + warp_n;
            g_bd2[(size_t)grp * TOKS + tok0 + row] = make_float2(d1, d2);
            g_bi2[(size_t)grp * TOKS + tok0 + row] = make_int2(c1, c2);
        }
    }
}

// ---------------- merge groups + exact rescore (thread per token) ----------------
__global__ __launch_bounds__(256) void merge_kernel(
    const float* __restrict__ ze, const float* __restrict__ cb,
    float* __restrict__ out, int out_size)
{
    int tok = blockIdx.x * 256 + threadIdx.x;
    if (tok >= TOKS) return;

    float cv[NCAND]; int ci[NCAND];
#pragma unroll
    for (int gp = 0; gp < NGROUP; ++gp) {
        float2 dv = g_bd2[(size_t)gp * TOKS + tok];
        int2   iv = g_bi2[(size_t)gp * TOKS + tok];
        cv[gp * 2 + 0] = dv.x; ci[gp * 2 + 0] = iv.x;
        cv[gp * 2 + 1] = dv.y; ci[gp * 2 + 1] = iv.y;
    }
    float b1v = cv[0]; int b1i = ci[0];
#pragma unroll
    for (int j = 1; j < NCAND; ++j)
        if (cmpdc(cv[j], ci[j], b1v, b1i)) { b1v = cv[j]; b1i = ci[j]; }
    int nwin = 0;
#pragma unroll
    for (int j = 0; j < NCAND; ++j)
        if (cv[j] <= b1v + TAU) ++nwin;

    int winner = b1i;
    if (nwin > 1) {
        const float4* xr = (const float4*)(ze + (size_t)tok * DIMD);
        float bd = 3.4e38f; int bi = 0x7fffffff;
#pragma unroll 1
        for (int j = 0; j < NCAND; ++j) {
            if (cv[j] > b1v + TAU) continue;
            int c = ci[j];
            const float4* cr = (const float4*)(cb + (size_t)c * DIMD);
            float dot = 0.f;
#pragma unroll
            for (int k = 0; k < 32; ++k) {
                float4 a = xr[k], b = cr[k];
                dot = fmaf(a.x, b.x, dot);
                dot = fmaf(a.y, b.y, dot);
                dot = fmaf(a.z, b.z, dot);
                dot = fmaf(a.w, b.w, dot);
            }
            float d2 = fmaf(-2.f, dot, __ldg(&g_cnorm[c]));
            if (d2 < bd || (d2 == bd && c < bi)) { bd = d2; bi = c; }
        }
        winner = bi;
    }
    g_idx[tok] = winner;
    if (out_size > TOKS * DIMD)
        out[(size_t)TOKS * DIMD + tok] = (float)winner;
}

// ---------------- gather: warp per token (broadcast idx, coalesced copy) --------
__global__ __launch_bounds__(256) void gather_kernel(
    const float* __restrict__ cb, float* __restrict__ out)
{
    int gid  = blockIdx.x * 256 + threadIdx.x;   // one float4 per thread
    int tok  = gid >> 5;
    int lane = gid & 31;
    int idx  = __ldg(&g_idx[tok]);
    ((float4*)out)[gid] = ((const float4*)cb)[(size_t)idx * 32 + lane];
}

extern "C" void kernel_launch(void* const* d_in, const int* in_sizes, int n_in,
                              void* d_out, int out_size) {
    const float* ze = (const float*)d_in[0];
    const float* cb = (const float*)d_in[1];
    if (n_in >= 2 && in_sizes[0] == KCB * DIMD && in_sizes[1] == TOKS * DIMD) {
        const float* tmp = ze; ze = cb; cb = tmp;
    }

    cudaFuncSetAttribute(vq_kernel, cudaFuncAttributeMaxDynamicSharedMemorySize,
                         SMEM_TOTAL);

    prep_kernel<<<(KCB / 8) * 32 / 256, 256>>>(cb);
    vq_kernel<<<NTILES * NQ, 256, SMEM_TOTAL>>>(ze);
    merge_kernel<<<TOKS / 256, 256>>>(ze, cb, (float*)d_out, out_size);
    gather_kernel<<<TOKS * 32 / 256, 256>>>(cb, (float*)d_out);
}